// round 7
// baseline (speedup 1.0000x reference)
#include <cuda_runtime.h>
#include <cuda_fp16.h>
#include <cstdint>

#define N_NODES_C 150000
#define N_EDGES_C 300000
#define N_LG_C    600000
#define HID       256
#define NGRAPH    2048
#define AFD       35
#define BFD       5
#define KIN       40

// ---------------- scratch (static device globals; no allocation) ----------------
__device__ float g_msg_input[(size_t)N_EDGES_C * HID];
__device__ float g_msg      [(size_t)N_EDGES_C * HID];
__device__ float g_msgB     [(size_t)N_EDGES_C * HID];
__device__ float g_alpha    [(size_t)N_NODES_C * HID];
__device__ float g_hbias    [(size_t)N_NODES_C * HID];
__device__ __half g_WhT_hi  [HID * HID];
__device__ __half g_WhT_lo  [HID * HID];
__device__ __half g_WoT_hi  [HID * HID];
__device__ __half g_WoT_lo  [HID * HID];
__device__ float g_counts   [NGRAPH];

// CSR structures
__device__ int g_lg_rowptr[N_EDGES_C + 1];
__device__ int g_lg_cursor[N_EDGES_C];
__device__ int g_lg_csr[N_LG_C];
__device__ int g_nd_rowptr[N_NODES_C + 1];
__device__ int g_nd_cursor[N_NODES_C];
__device__ int g_nd_csr[N_EDGES_C];
__device__ int g_part [1024];
__device__ int g_part2[1024];

// ---------------- PTX helpers (portable: sm_80/sm_90 level only) ----------------
__device__ __forceinline__ uint32_t smem_u32(const void* p) {
    uint32_t a;
    asm("{ .reg .u64 t; cvta.to.shared.u64 t, %1; cvt.u32.u64 %0, t; }" : "=r"(a) : "l"(p));
    return a;
}
__device__ __forceinline__ void red4(float* p, float a, float b, float c, float d) {
    asm volatile("red.global.add.v4.f32 [%0], {%1, %2, %3, %4};"
                 :: "l"(p), "f"(a), "f"(b), "f"(c), "f"(d) : "memory");
}
__device__ __forceinline__ void red2(float* p, float a, float b) {
    asm volatile("red.global.add.v2.f32 [%0], {%1, %2};"
                 :: "l"(p), "f"(a), "f"(b) : "memory");
}
__device__ __forceinline__ void ldsm4(uint32_t* r, uint32_t addr) {
    asm volatile("ldmatrix.sync.aligned.m8n8.x4.shared.b16 {%0,%1,%2,%3}, [%4];"
                 : "=r"(r[0]), "=r"(r[1]), "=r"(r[2]), "=r"(r[3]) : "r"(addr));
}
__device__ __forceinline__ void ldsm2(uint32_t* r, uint32_t addr) {
    asm volatile("ldmatrix.sync.aligned.m8n8.x2.shared.b16 {%0,%1}, [%2];"
                 : "=r"(r[0]), "=r"(r[1]) : "r"(addr));
}
__device__ __forceinline__ void mma_f16(float* d, const uint32_t* a, const uint32_t* b) {
    asm volatile(
        "mma.sync.aligned.m16n8k16.row.col.f32.f16.f16.f32 "
        "{%0,%1,%2,%3}, {%4,%5,%6,%7}, {%8,%9}, {%0,%1,%2,%3};"
        : "+f"(d[0]), "+f"(d[1]), "+f"(d[2]), "+f"(d[3])
        : "r"(a[0]), "r"(a[1]), "r"(a[2]), "r"(a[3]), "r"(b[0]), "r"(b[1]));
}
__device__ __forceinline__ uint32_t h2u(__half2 h) { return *reinterpret_cast<uint32_t*>(&h); }
__device__ __forceinline__ void cp16(uint32_t dst, const void* src) {
    asm volatile("cp.async.cg.shared.global [%0], [%1], 16;" :: "r"(dst), "l"(src));
}
#define CP_COMMIT() asm volatile("cp.async.commit_group;" ::: "memory")
#define CP_WAIT0()  asm volatile("cp.async.wait_group 0;" ::: "memory")

// ---------------- CSR build kernels ----------------
__global__ void k_zeroi(int* __restrict__ p, int n) {
    int i = blockIdx.x * 256 + threadIdx.x;
    if (i < n) p[i] = 0;
}
__global__ void k_hist(const int* __restrict__ dst, int* __restrict__ cnt, int n) {
    int i = blockIdx.x * 256 + threadIdx.x;
    if (i < n) atomicAdd(&cnt[dst[i]], 1);
}
__global__ void k_scan1(const int* __restrict__ cnt, int* __restrict__ ex, int n,
                        int* __restrict__ part) {
    __shared__ int sh[256];
    int base = blockIdx.x * 1024;
    int t = threadIdx.x;
    int v[4], s = 0;
#pragma unroll
    for (int j = 0; j < 4; j++) {
        int i = base + t * 4 + j;
        v[j] = (i < n) ? cnt[i] : 0;
        s += v[j];
    }
    sh[t] = s;
    __syncthreads();
    for (int off = 1; off < 256; off <<= 1) {
        int x = (t >= off) ? sh[t - off] : 0;
        __syncthreads();
        sh[t] += x;
        __syncthreads();
    }
    int run = (t > 0) ? sh[t - 1] : 0;
    if (part && t == 255) part[blockIdx.x] = sh[255];
#pragma unroll
    for (int j = 0; j < 4; j++) {
        int i = base + t * 4 + j;
        if (i < n) ex[i] = run;
        run += v[j];
    }
}
__global__ void k_scan3(int* __restrict__ ex, int* __restrict__ cursor,
                        const int* __restrict__ part2, int n, int ntot) {
    int i = blockIdx.x * 256 + threadIdx.x;
    if (i < n) {
        int v = ex[i] + part2[i >> 10];
        ex[i] = v;
        cursor[i] = v;
    }
    if (i == 0) ex[n] = ntot;
}
__global__ void k_fill(const int* __restrict__ src, const int* __restrict__ dst,
                       int* __restrict__ cursor, int* __restrict__ csr, int n) {
    int i = blockIdx.x * 256 + threadIdx.x;
    if (i < n) {
        int pos = atomicAdd(&cursor[dst[i]], 1);
        csr[pos] = src[i];
    }
}
__global__ void k_fill_id(const int* __restrict__ dst, int* __restrict__ cursor,
                          int* __restrict__ csr, int n) {
    int i = blockIdx.x * 256 + threadIdx.x;
    if (i < n) {
        int pos = atomicAdd(&cursor[dst[i]], 1);
        csr[pos] = i;
    }
}

// ---------------- utility kernels ----------------
__global__ void k_zero_alpha() {
    int i = blockIdx.x * 256 + threadIdx.x;
    ((float4*)g_alpha)[i] = make_float4(0.f, 0.f, 0.f, 0.f);
}
__global__ void k_zero_out(float* __restrict__ out) {
    int i = blockIdx.x * 256 + threadIdx.x;
    ((float4*)out)[i] = make_float4(0.f, 0.f, 0.f, 0.f);
    if (i < NGRAPH) g_counts[i] = 0.f;
}
__global__ void k_counts(const int* __restrict__ gids) {
    int v = blockIdx.x * 256 + threadIdx.x;
    if (v < N_NODES_C) atomicAdd(&g_counts[gids[v]], 1.0f);
}
__global__ void k_div(float* __restrict__ out) {
    int i = blockIdx.x * 256 + threadIdx.x;
    int g = i >> 6;
    float c = fmaxf(g_counts[g], 1.0f);
    float4 v = ((float4*)out)[i];
    v.x /= c; v.y /= c; v.z /= c; v.w /= c;
    ((float4*)out)[i] = v;
}
// pre-split W to fp16 hi/lo, transposed to [n][k]
__global__ void k_prep_w(const float* __restrict__ Wh, const float* __restrict__ Wo) {
    int n = blockIdx.x & 255;
    int k = threadIdx.x;
    float v;
    __half* hi;
    __half* lo;
    if (blockIdx.x < 256) { v = Wh[k * 256 + n];         hi = g_WhT_hi; lo = g_WhT_lo; }
    else                  { v = Wo[(AFD + k) * 256 + n]; hi = g_WoT_hi; lo = g_WoT_lo; }
    __half h = __float2half_rn(v);
    hi[n * 256 + k] = h;
    lo[n * 256 + k] = __float2half_rn(v - __half2float(h));
}
__global__ void k_tree_scatter(const float* __restrict__ tree, const int* __restrict__ tgt) {
    int i = blockIdx.x * 256 + threadIdx.x;
    int t = i >> 6, q = i & 63;
    float4 v = ((const float4*)tree)[(size_t)t * 64 + q];
    red4(g_alpha + (size_t)tgt[t] * HID + q * 4, v.x, v.y, v.z, v.w);
}

// ---------------- msg_input = [node_x[src]; bond_x] @ W_i ----------------
__global__ __launch_bounds__(256)
void k_msg_in(const float* __restrict__ node_x, const float* __restrict__ bond_x,
              const float* __restrict__ W_i, const int* __restrict__ esrc) {
    __shared__ float feat[64][KIN];
    int e0 = blockIdx.x * 64;
    int tid = threadIdx.x;
    float w[KIN];
#pragma unroll
    for (int k = 0; k < KIN; k++) w[k] = W_i[k * HID + tid];
    for (int idx = tid; idx < 64 * KIN; idx += 256) {
        int e = idx / KIN, k = idx % KIN;
        int ge = e0 + e;
        float vv = 0.f;
        if (ge < N_EDGES_C)
            vv = (k < AFD) ? node_x[(size_t)esrc[ge] * AFD + k]
                           : bond_x[(size_t)ge * BFD + (k - AFD)];
        feat[e][k] = vv;
    }
    __syncthreads();
    for (int e = 0; e < 64; e++) {
        int ge = e0 + e;
        if (ge >= N_EDGES_C) break;
        const float4* f4 = (const float4*)feat[e];
        float a0 = 0.f, a1 = 0.f;
#pragma unroll
        for (int k4 = 0; k4 < KIN / 4; k4++) {
            float4 ff = f4[k4];
            a0 = fmaf(ff.x, w[k4 * 4 + 0], a0);
            a1 = fmaf(ff.y, w[k4 * 4 + 1], a1);
            a0 = fmaf(ff.z, w[k4 * 4 + 2], a0);
            a1 = fmaf(ff.w, w[k4 * 4 + 3], a1);
        }
        g_msg_input[(size_t)ge * HID + tid] = a0 + a1;
    }
}

// ---------------- g_hbias = node_x @ W_o[:35] + b_o ----------------
__global__ __launch_bounds__(256)
void k_hbias(const float* __restrict__ node_x, const float* __restrict__ W_o,
             const float* __restrict__ b_o) {
    __shared__ float feat[64][36];
    int v0 = blockIdx.x * 64;
    int tid = threadIdx.x;
    float w[36];
#pragma unroll
    for (int k = 0; k < AFD; k++) w[k] = W_o[k * HID + tid];
    w[35] = 0.f;
    float bb = b_o[tid];
    for (int idx = tid; idx < 64 * 36; idx += 256) {
        int v = idx / 36, k = idx % 36;
        int gv = v0 + v;
        feat[v][k] = (gv < N_NODES_C && k < AFD) ? node_x[(size_t)gv * AFD + k] : 0.f;
    }
    __syncthreads();
    for (int v = 0; v < 64; v++) {
        int gv = v0 + v;
        if (gv >= N_NODES_C) break;
        const float4* f4 = (const float4*)feat[v];
        float a0 = bb, a1 = 0.f;
#pragma unroll
        for (int k4 = 0; k4 < 9; k4++) {
            float4 ff = f4[k4];
            a0 = fmaf(ff.x, w[k4 * 4 + 0], a0);
            a1 = fmaf(ff.y, w[k4 * 4 + 1], a1);
            a0 = fmaf(ff.z, w[k4 * 4 + 2], a0);
            a1 = fmaf(ff.w, w[k4 * 4 + 3], a1);
        }
        g_hbias[(size_t)gv * HID + tid] = a0 + a1;
    }
}

// ---------------- fused gather + fp16-split GEMM ----------------
// A[row] = alpha[ridx(row)] + sum_{csr} (relu?) srcmsg[s]   (gathered per k-chunk)
// D[128,256] = A @ B^T with 2-term fp16 split (3 mma terms), B pre-split hi/lo.
// MODE 0: dst = relu(bias + D)            (per-edge;  ridx = esrc)
// MODE 1: out[gids[row]] += relu(bias+D)  (per-node;  ridx = identity)
// SMEM per buffer: Ahi 16K | Alo 16K | Bhi 32K | Blo 32K = 96K, double-buffered.
#define MMF_BUF  98304
#define MMF_SMEM (2 * MMF_BUF)

template<int MODE, bool FIRST>
__global__ __launch_bounds__(512, 1)
void k_mmf(const int* __restrict__ ridx, const int* __restrict__ rowptr,
           const int* __restrict__ csr, const float* __restrict__ srcmsg,
           const float* __restrict__ bias,
           const __half* __restrict__ Bhi, const __half* __restrict__ Blo,
           float* __restrict__ dst, const int* __restrict__ gids,
           float* __restrict__ out, int M) {
    extern __shared__ char sm[];
    const int tid  = threadIdx.x;
    const int lane = tid & 31;
    const int wid  = tid >> 5;
    const int wm   = wid >> 2;       // 0..3 : 32-row band
    const int wn   = wid & 3;        // 0..3 : 64-col band
    const int m0   = blockIdx.x * 128;
    const uint32_t sbase = smem_u32(sm);

    float d[2][8][4];
#pragma unroll
    for (int i = 0; i < 2; i++)
#pragma unroll
        for (int j = 0; j < 8; j++)
#pragma unroll
            for (int q = 0; q < 4; q++) d[i][j][q] = 0.f;

    float4 pfA[4];

    // gather A chunk cc into registers
    auto gatherA = [&](int cc) {
#pragma unroll
        for (int j = 0; j < 4; j++) {
            int idx = tid + j * 512;            // 0..2047
            int row = idx >> 4, seg = idx & 15; // 16 float4-segs = 64 floats
            int gm = m0 + row;
            float4 acc = make_float4(0.f, 0.f, 0.f, 0.f);
            if (gm < M) {
                int ar = (MODE == 0) ? __ldg(&ridx[gm]) : gm;
                acc = __ldg((const float4*)g_alpha + (size_t)ar * 64 + cc * 16 + seg);
                int p0 = __ldg(&rowptr[gm]);
                int p1 = __ldg(&rowptr[gm + 1]);
                for (int p = p0; p < p1; p++) {
                    int s = __ldg(&csr[p]);
                    float4 v = __ldg((const float4*)srcmsg + (size_t)s * 64 + cc * 16 + seg);
                    if (FIRST) {
                        v.x = fmaxf(v.x, 0.f); v.y = fmaxf(v.y, 0.f);
                        v.z = fmaxf(v.z, 0.f); v.w = fmaxf(v.w, 0.f);
                    }
                    acc.x += v.x; acc.y += v.y; acc.z += v.z; acc.w += v.w;
                }
            }
            pfA[j] = acc;
        }
    };
    // split + store A chunk to buffer b
    auto stsA = [&](int b) {
        char* buf = sm + b * MMF_BUF;
#pragma unroll
        for (int j = 0; j < 4; j++) {
            int idx = tid + j * 512;
            int row = idx >> 4, seg = idx & 15;
            uint32_t off = (uint32_t)(row * 128 + seg * 8);
            uint32_t sw = off ^ ((off >> 3) & 0x70);
            float4 v = pfA[j];
            __half2 h01 = __floats2half2_rn(v.x, v.y);
            __half2 h23 = __floats2half2_rn(v.z, v.w);
            __half2 l01 = __floats2half2_rn(v.x - __low2float(h01), v.y - __high2float(h01));
            __half2 l23 = __floats2half2_rn(v.z - __low2float(h23), v.w - __high2float(h23));
            *(uint2*)(buf + sw)         = make_uint2(h2u(h01), h2u(h23));
            *(uint2*)(buf + 16384 + sw) = make_uint2(h2u(l01), h2u(l23));
        }
    };
    // async-stage B chunk cc (hi+lo, 256 rows x 64 halves each) to buffer b
    auto cpB = [&](int cc, int b) {
        uint32_t base = sbase + b * MMF_BUF;
#pragma unroll
        for (int j = 0; j < 8; j++) {
            int idx = tid + j * 512;            // 0..4095
            int u = idx & 2047;
            int row = u >> 3, seg = u & 7;      // 8 x 16B = 128B per row
            uint32_t off = (uint32_t)(row * 128 + seg * 16);
            uint32_t sw = off ^ ((off >> 3) & 0x70);
            const __half* src = (idx < 2048) ? Bhi : Blo;
            uint32_t dsm = base + ((idx < 2048) ? 32768u : 65536u) + sw;
            cp16(dsm, src + (size_t)row * 256 + cc * 64 + seg * 8);
        }
        CP_COMMIT();
    };
    auto compute = [&](int b) {
        uint32_t baseA  = sbase + b * MMF_BUF;
        uint32_t baseAl = baseA + 16384;
        uint32_t baseBh = baseA + 32768;
        uint32_t baseBl = baseA + 65536;
        const int r = lane & 7, q = lane >> 3;
#pragma unroll
        for (int s = 0; s < 4; s++) {
            uint32_t ah[2][4], al[2][4];
#pragma unroll
            for (int mt = 0; mt < 2; mt++) {
                uint32_t mrow = (uint32_t)(wm * 32 + mt * 16 + (q & 1) * 8 + r);
                uint32_t off = mrow * 128 + (q >> 1) * 16 + s * 32;
                uint32_t sw = off ^ ((off >> 3) & 0x70);
                ldsm4(ah[mt], baseA + sw);
                ldsm4(al[mt], baseAl + sw);
            }
#pragma unroll
            for (int h = 0; h < 2; h++) {
                uint32_t bh[4][2], bl[4][2];
#pragma unroll
                for (int nt = 0; nt < 4; nt++) {
                    uint32_t nrow = (uint32_t)(wn * 64 + h * 32 + nt * 8 + r);
                    uint32_t off = nrow * 128 + (q & 1) * 16 + s * 32;
                    uint32_t sw = off ^ ((off >> 3) & 0x70);
                    ldsm2(bh[nt], baseBh + sw);
                    ldsm2(bl[nt], baseBl + sw);
                }
#pragma unroll
                for (int mt = 0; mt < 2; mt++)
#pragma unroll
                    for (int nt = 0; nt < 4; nt++) {
                        float* acc = d[mt][h * 4 + nt];
                        mma_f16(acc, ah[mt], bh[nt]);
                        mma_f16(acc, ah[mt], bl[nt]);
                        mma_f16(acc, al[mt], bh[nt]);
                    }
            }
        }
    };

    // prologue
    cpB(0, 0);
    gatherA(0);
    stsA(0);
    CP_WAIT0();
    __syncthreads();

#pragma unroll
    for (int c = 0; c < 4; c++) {
        if (c < 3) {
            cpB(c + 1, (c + 1) & 1);
            gatherA(c + 1);
        }
        compute(c & 1);
        if (c < 3) stsA((c + 1) & 1);
        CP_WAIT0();
        __syncthreads();
    }

    // epilogue
#pragma unroll
    for (int mt = 0; mt < 2; mt++) {
#pragma unroll
        for (int n = 0; n < 8; n++) {
            int row = m0 + wm * 32 + mt * 16 + (lane >> 2);
            int col = wn * 64 + n * 8 + (lane & 3) * 2;
#pragma unroll
            for (int h2 = 0; h2 < 2; h2++) {
                int gr = row + h2 * 8;
                if (gr >= M) continue;
                size_t gb = (size_t)gr * 256 + col;
                float2 bv = *(const float2*)(bias + gb);
                float ox = fmaxf(bv.x + d[mt][n][h2 * 2 + 0], 0.f);
                float oy = fmaxf(bv.y + d[mt][n][h2 * 2 + 1], 0.f);
                if (MODE == 0) {
                    *(float2*)(dst + gb) = make_float2(ox, oy);
                } else {
                    int g = gids[gr];
                    red2(out + (size_t)g * 256 + col, ox, oy);
                }
            }
        }
    }
}

// ---------------- launch ----------------
extern "C" void kernel_launch(void* const* d_in, const int* in_sizes, int n_in,
                              void* d_out, int out_size) {
    (void)in_sizes; (void)n_in; (void)out_size;
    const float* node_x = (const float*)d_in[0];
    const float* bond_x = (const float*)d_in[1];
    const float* tree   = (const float*)d_in[2];
    const float* W_i    = (const float*)d_in[3];
    const float* W_h    = (const float*)d_in[4];
    const float* W_o    = (const float*)d_in[5];
    const float* b_o    = (const float*)d_in[6];
    const int* esrc = (const int*)d_in[7];
    const int* edst = (const int*)d_in[8];
    const int* lsrc = (const int*)d_in[9];
    const int* ldst = (const int*)d_in[10];
    const int* tgt  = (const int*)d_in[11];
    const int* gids = (const int*)d_in[12];
    float* out = (float*)d_out;

    cudaFuncSetAttribute(k_mmf<0, true>,  cudaFuncAttributeMaxDynamicSharedMemorySize, MMF_SMEM);
    cudaFuncSetAttribute(k_mmf<0, false>, cudaFuncAttributeMaxDynamicSharedMemorySize, MMF_SMEM);
    cudaFuncSetAttribute(k_mmf<1, false>, cudaFuncAttributeMaxDynamicSharedMemorySize, MMF_SMEM);

    float *hb_p, *mi_p, *msg_p, *msgB_p;
    cudaGetSymbolAddress((void**)&hb_p,   g_hbias);
    cudaGetSymbolAddress((void**)&mi_p,   g_msg_input);
    cudaGetSymbolAddress((void**)&msg_p,  g_msg);
    cudaGetSymbolAddress((void**)&msgB_p, g_msgB);
    __half *WhH, *WhL, *WoH, *WoL;
    cudaGetSymbolAddress((void**)&WhH, g_WhT_hi);
    cudaGetSymbolAddress((void**)&WhL, g_WhT_lo);
    cudaGetSymbolAddress((void**)&WoH, g_WoT_hi);
    cudaGetSymbolAddress((void**)&WoL, g_WoT_lo);
    int *lg_rp, *lg_cur, *lg_csr_p, *nd_rp, *nd_cur, *nd_csr_p, *part_p, *part2_p;
    cudaGetSymbolAddress((void**)&lg_rp,    g_lg_rowptr);
    cudaGetSymbolAddress((void**)&lg_cur,   g_lg_cursor);
    cudaGetSymbolAddress((void**)&lg_csr_p, g_lg_csr);
    cudaGetSymbolAddress((void**)&nd_rp,    g_nd_rowptr);
    cudaGetSymbolAddress((void**)&nd_cur,   g_nd_cursor);
    cudaGetSymbolAddress((void**)&nd_csr_p, g_nd_csr);
    cudaGetSymbolAddress((void**)&part_p,   g_part);
    cudaGetSymbolAddress((void**)&part2_p,  g_part2);

    // ---- CSR build: line graph (buckets = ldst over N_EDGES) ----
    k_zeroi<<<1172, 256>>>(lg_cur, N_EDGES_C);
    k_hist<<<2344, 256>>>(ldst, lg_cur, N_LG_C);
    k_scan1<<<293, 256>>>(lg_cur, lg_rp, N_EDGES_C, part_p);
    k_scan1<<<1, 256>>>(part_p, part2_p, 293, nullptr);
    k_scan3<<<1172, 256>>>(lg_rp, lg_cur, part2_p, N_EDGES_C, N_LG_C);
    k_fill<<<2344, 256>>>(lsrc, ldst, lg_cur, lg_csr_p, N_LG_C);
    // ---- CSR build: node graph (buckets = edge_dst over N_NODES; values = edge id) ----
    k_zeroi<<<586, 256>>>(nd_cur, N_NODES_C);
    k_hist<<<1172, 256>>>(edst, nd_cur, N_EDGES_C);
    k_scan1<<<147, 256>>>(nd_cur, nd_rp, N_NODES_C, part_p);
    k_scan1<<<1, 256>>>(part_p, part2_p, 147, nullptr);
    k_scan3<<<586, 256>>>(nd_rp, nd_cur, part2_p, N_NODES_C, N_EDGES_C);
    k_fill_id<<<1172, 256>>>(edst, nd_cur, nd_csr_p, N_EDGES_C);

    k_prep_w<<<512, 256>>>(W_h, W_o);
    k_zero_alpha<<<37500, 256>>>();
    k_zero_out<<<512, 256>>>(out);
    k_tree_scatter<<<15000, 256>>>(tree, tgt);
    k_msg_in<<<(N_EDGES_C + 63) / 64, 256>>>(node_x, bond_x, W_i, esrc);
    k_hbias<<<(N_NODES_C + 63) / 64, 256>>>(node_x, W_o, b_o);

    // BP iterations: msg ping-pong (msg_input -> msg -> msgB -> msg)
    k_mmf<0, true><<<2344, 512, MMF_SMEM>>>(esrc, lg_rp, lg_csr_p, mi_p,  mi_p,
                                            WhH, WhL, msg_p,  nullptr, nullptr, N_EDGES_C);
    k_mmf<0, false><<<2344, 512, MMF_SMEM>>>(esrc, lg_rp, lg_csr_p, msg_p, mi_p,
                                             WhH, WhL, msgB_p, nullptr, nullptr, N_EDGES_C);
    k_mmf<0, false><<<2344, 512, MMF_SMEM>>>(esrc, lg_rp, lg_csr_p, msgB_p, mi_p,
                                             WhH, WhL, msg_p,  nullptr, nullptr, N_EDGES_C);

    k_counts<<<586, 256>>>(gids);
    k_mmf<1, false><<<1172, 512, MMF_SMEM>>>(nullptr, nd_rp, nd_csr_p, msg_p, hb_p,
                                             WoH, WoL, nullptr, gids, out, N_NODES_C);
    k_div<<<512, 256>>>(out);
}

// round 8
// speedup vs baseline: 1.2897x; 1.2897x over previous
#include <cuda_runtime.h>
#include <cuda_fp16.h>
#include <cstdint>

#define N_NODES_C 150000
#define N_EDGES_C 300000
#define N_LG_C    600000
#define HID       256
#define NGRAPH    2048
#define AFD       35
#define BFD       5
#define KIN       40

// ---------------- scratch (static device globals; no allocation) ----------------
__device__ float g_msg_input[(size_t)N_EDGES_C * HID];
__device__ float g_msg      [(size_t)N_EDGES_C * HID];
__device__ float g_accum    [(size_t)N_EDGES_C * HID];
__device__ float g_alpha    [(size_t)N_NODES_C * HID];
__device__ float g_mplus    [(size_t)N_NODES_C * HID];
__device__ float g_hbias    [(size_t)N_NODES_C * HID];
__device__ __half g_WhT_hi  [HID * HID];
__device__ __half g_WhT_lo  [HID * HID];
__device__ __half g_WoT_hi  [HID * HID];
__device__ __half g_WoT_lo  [HID * HID];
__device__ float g_counts   [NGRAPH];

// CSR structures
__device__ int g_lg_rowptr[N_EDGES_C + 1];
__device__ int g_lg_cursor[N_EDGES_C];
__device__ int g_lg_csr[N_LG_C];
__device__ int g_nd_rowptr[N_NODES_C + 1];
__device__ int g_nd_cursor[N_NODES_C];
__device__ int g_nd_csr[N_EDGES_C];
__device__ int g_part [1024];
__device__ int g_part2[1024];

// ---------------- PTX helpers (portable: sm_80/sm_90 level only) ----------------
__device__ __forceinline__ uint32_t smem_u32(const void* p) {
    uint32_t a;
    asm("{ .reg .u64 t; cvta.to.shared.u64 t, %1; cvt.u32.u64 %0, t; }" : "=r"(a) : "l"(p));
    return a;
}
__device__ __forceinline__ void red4(float* p, float a, float b, float c, float d) {
    asm volatile("red.global.add.v4.f32 [%0], {%1, %2, %3, %4};"
                 :: "l"(p), "f"(a), "f"(b), "f"(c), "f"(d) : "memory");
}
__device__ __forceinline__ void red2(float* p, float a, float b) {
    asm volatile("red.global.add.v2.f32 [%0], {%1, %2};"
                 :: "l"(p), "f"(a), "f"(b) : "memory");
}
__device__ __forceinline__ void ldsm4(uint32_t* r, uint32_t addr) {
    asm volatile("ldmatrix.sync.aligned.m8n8.x4.shared.b16 {%0,%1,%2,%3}, [%4];"
                 : "=r"(r[0]), "=r"(r[1]), "=r"(r[2]), "=r"(r[3]) : "r"(addr));
}
__device__ __forceinline__ void ldsm2(uint32_t* r, uint32_t addr) {
    asm volatile("ldmatrix.sync.aligned.m8n8.x2.shared.b16 {%0,%1}, [%2];"
                 : "=r"(r[0]), "=r"(r[1]) : "r"(addr));
}
__device__ __forceinline__ void mma_f16(float* d, const uint32_t* a, const uint32_t* b) {
    asm volatile(
        "mma.sync.aligned.m16n8k16.row.col.f32.f16.f16.f32 "
        "{%0,%1,%2,%3}, {%4,%5,%6,%7}, {%8,%9}, {%0,%1,%2,%3};"
        : "+f"(d[0]), "+f"(d[1]), "+f"(d[2]), "+f"(d[3])
        : "r"(a[0]), "r"(a[1]), "r"(a[2]), "r"(a[3]), "r"(b[0]), "r"(b[1]));
}
__device__ __forceinline__ uint32_t h2u(__half2 h) { return *reinterpret_cast<uint32_t*>(&h); }
__device__ __forceinline__ void cp16(uint32_t dst, const void* src) {
    asm volatile("cp.async.cg.shared.global [%0], [%1], 16;" :: "r"(dst), "l"(src));
}
#define CP_COMMIT() asm volatile("cp.async.commit_group;" ::: "memory")
#define CP_WAIT0()  asm volatile("cp.async.wait_group 0;" ::: "memory")

// ---------------- CSR build kernels ----------------
__global__ void k_zeroi(int* __restrict__ p, int n) {
    int i = blockIdx.x * 256 + threadIdx.x;
    if (i < n) p[i] = 0;
}
__global__ void k_hist(const int* __restrict__ dst, int* __restrict__ cnt, int n) {
    int i = blockIdx.x * 256 + threadIdx.x;
    if (i < n) atomicAdd(&cnt[dst[i]], 1);
}
__global__ void k_scan1(const int* __restrict__ cnt, int* __restrict__ ex, int n,
                        int* __restrict__ part) {
    __shared__ int sh[256];
    int base = blockIdx.x * 1024;
    int t = threadIdx.x;
    int v[4], s = 0;
#pragma unroll
    for (int j = 0; j < 4; j++) {
        int i = base + t * 4 + j;
        v[j] = (i < n) ? cnt[i] : 0;
        s += v[j];
    }
    sh[t] = s;
    __syncthreads();
    for (int off = 1; off < 256; off <<= 1) {
        int x = (t >= off) ? sh[t - off] : 0;
        __syncthreads();
        sh[t] += x;
        __syncthreads();
    }
    int run = (t > 0) ? sh[t - 1] : 0;
    if (part && t == 255) part[blockIdx.x] = sh[255];
#pragma unroll
    for (int j = 0; j < 4; j++) {
        int i = base + t * 4 + j;
        if (i < n) ex[i] = run;
        run += v[j];
    }
}
__global__ void k_scan3(int* __restrict__ ex, int* __restrict__ cursor,
                        const int* __restrict__ part2, int n, int ntot) {
    int i = blockIdx.x * 256 + threadIdx.x;
    if (i < n) {
        int v = ex[i] + part2[i >> 10];
        ex[i] = v;
        cursor[i] = v;
    }
    if (i == 0) ex[n] = ntot;
}
__global__ void k_fill(const int* __restrict__ src, const int* __restrict__ dst,
                       int* __restrict__ cursor, int* __restrict__ csr, int n) {
    int i = blockIdx.x * 256 + threadIdx.x;
    if (i < n) {
        int pos = atomicAdd(&cursor[dst[i]], 1);
        csr[pos] = src[i];
    }
}
__global__ void k_fill_id(const int* __restrict__ dst, int* __restrict__ cursor,
                          int* __restrict__ csr, int n) {
    int i = blockIdx.x * 256 + threadIdx.x;
    if (i < n) {
        int pos = atomicAdd(&cursor[dst[i]], 1);
        csr[pos] = i;
    }
}

// ---------------- utility kernels ----------------
__global__ void k_zero_alpha() {
    int i = blockIdx.x * 256 + threadIdx.x;
    ((float4*)g_alpha)[i] = make_float4(0.f, 0.f, 0.f, 0.f);
}
__global__ void k_zero_out(float* __restrict__ out) {
    int i = blockIdx.x * 256 + threadIdx.x;
    ((float4*)out)[i] = make_float4(0.f, 0.f, 0.f, 0.f);
    if (i < NGRAPH) g_counts[i] = 0.f;
}
__global__ void k_counts(const int* __restrict__ gids) {
    int v = blockIdx.x * 256 + threadIdx.x;
    if (v < N_NODES_C) atomicAdd(&g_counts[gids[v]], 1.0f);
}
__global__ void k_div(float* __restrict__ out) {
    int i = blockIdx.x * 256 + threadIdx.x;
    int g = i >> 6;
    float c = fmaxf(g_counts[g], 1.0f);
    float4 v = ((float4*)out)[i];
    v.x /= c; v.y /= c; v.z /= c; v.w /= c;
    ((float4*)out)[i] = v;
}
// pre-split W to fp16 hi/lo, transposed to [n][k]
__global__ void k_prep_w(const float* __restrict__ Wh, const float* __restrict__ Wo) {
    int n = blockIdx.x & 255;
    int k = threadIdx.x;
    float v;
    __half* hi;
    __half* lo;
    if (blockIdx.x < 256) { v = Wh[k * 256 + n];         hi = g_WhT_hi; lo = g_WhT_lo; }
    else                  { v = Wo[(AFD + k) * 256 + n]; hi = g_WoT_hi; lo = g_WoT_lo; }
    __half h = __float2half_rn(v);
    hi[n * 256 + k] = h;
    lo[n * 256 + k] = __float2half_rn(v - __half2float(h));
}
__global__ void k_tree_scatter(const float* __restrict__ tree, const int* __restrict__ tgt) {
    int i = blockIdx.x * 256 + threadIdx.x;
    int t = i >> 6, q = i & 63;
    float4 v = ((const float4*)tree)[(size_t)t * 64 + q];
    red4(g_alpha + (size_t)tgt[t] * HID + q * 4, v.x, v.y, v.z, v.w);
}

// ---------------- CSR gather: accum[e] = alpha[esrc[e]] + sum msg[lg_csr[...]] --------
template<bool FIRST>
__global__ __launch_bounds__(256)
void k_lg_gather(const int* __restrict__ esrc) {
    int i = blockIdx.x * 256 + threadIdx.x;
    int e = i >> 6, q = i & 63;
    int a = __ldg(&esrc[e]);
    float4 acc = ((const float4*)g_alpha)[(size_t)a * 64 + q];
    int beg = __ldg(&g_lg_rowptr[e]);
    int end = __ldg(&g_lg_rowptr[e + 1]);
    const float4* src = FIRST ? (const float4*)g_msg_input : (const float4*)g_msg;
    for (int j = beg; j < end; j++) {
        int s = __ldg(&g_lg_csr[j]);
        float4 v = src[(size_t)s * 64 + q];
        if (FIRST) {
            v.x = fmaxf(v.x, 0.f); v.y = fmaxf(v.y, 0.f);
            v.z = fmaxf(v.z, 0.f); v.w = fmaxf(v.w, 0.f);
        }
        acc.x += v.x; acc.y += v.y; acc.z += v.z; acc.w += v.w;
    }
    ((float4*)g_accum)[(size_t)e * 64 + q] = acc;
}

// mplus[v] = alpha[v] + sum msg[nd_csr[...]]
__global__ __launch_bounds__(256)
void k_node_gather() {
    int i = blockIdx.x * 256 + threadIdx.x;
    int v = i >> 6, q = i & 63;
    float4 acc = ((const float4*)g_alpha)[(size_t)v * 64 + q];
    int beg = __ldg(&g_nd_rowptr[v]);
    int end = __ldg(&g_nd_rowptr[v + 1]);
    for (int j = beg; j < end; j++) {
        int s = __ldg(&g_nd_csr[j]);
        float4 m = ((const float4*)g_msg)[(size_t)s * 64 + q];
        acc.x += m.x; acc.y += m.y; acc.z += m.z; acc.w += m.w;
    }
    ((float4*)g_mplus)[(size_t)v * 64 + q] = acc;
}

// ---------------- msg_input = [node_x[src]; bond_x] @ W_i ----------------
__global__ __launch_bounds__(256)
void k_msg_in(const float* __restrict__ node_x, const float* __restrict__ bond_x,
              const float* __restrict__ W_i, const int* __restrict__ esrc) {
    __shared__ float feat[64][KIN];
    int e0 = blockIdx.x * 64;
    int tid = threadIdx.x;
    float w[KIN];
#pragma unroll
    for (int k = 0; k < KIN; k++) w[k] = W_i[k * HID + tid];
    for (int idx = tid; idx < 64 * KIN; idx += 256) {
        int e = idx / KIN, k = idx % KIN;
        int ge = e0 + e;
        float vv = 0.f;
        if (ge < N_EDGES_C)
            vv = (k < AFD) ? node_x[(size_t)esrc[ge] * AFD + k]
                           : bond_x[(size_t)ge * BFD + (k - AFD)];
        feat[e][k] = vv;
    }
    __syncthreads();
    for (int e = 0; e < 64; e++) {
        int ge = e0 + e;
        if (ge >= N_EDGES_C) break;
        const float4* f4 = (const float4*)feat[e];
        float a0 = 0.f, a1 = 0.f;
#pragma unroll
        for (int k4 = 0; k4 < KIN / 4; k4++) {
            float4 ff = f4[k4];
            a0 = fmaf(ff.x, w[k4 * 4 + 0], a0);
            a1 = fmaf(ff.y, w[k4 * 4 + 1], a1);
            a0 = fmaf(ff.z, w[k4 * 4 + 2], a0);
            a1 = fmaf(ff.w, w[k4 * 4 + 3], a1);
        }
        g_msg_input[(size_t)ge * HID + tid] = a0 + a1;
    }
}

// ---------------- g_hbias = node_x @ W_o[:35] + b_o ----------------
__global__ __launch_bounds__(256)
void k_hbias(const float* __restrict__ node_x, const float* __restrict__ W_o,
             const float* __restrict__ b_o) {
    __shared__ float feat[64][36];
    int v0 = blockIdx.x * 64;
    int tid = threadIdx.x;
    float w[36];
#pragma unroll
    for (int k = 0; k < AFD; k++) w[k] = W_o[k * HID + tid];
    w[35] = 0.f;
    float bb = b_o[tid];
    for (int idx = tid; idx < 64 * 36; idx += 256) {
        int v = idx / 36, k = idx % 36;
        int gv = v0 + v;
        feat[v][k] = (gv < N_NODES_C && k < AFD) ? node_x[(size_t)gv * AFD + k] : 0.f;
    }
    __syncthreads();
    for (int v = 0; v < 64; v++) {
        int gv = v0 + v;
        if (gv >= N_NODES_C) break;
        const float4* f4 = (const float4*)feat[v];
        float a0 = bb, a1 = 0.f;
#pragma unroll
        for (int k4 = 0; k4 < 9; k4++) {
            float4 ff = f4[k4];
            a0 = fmaf(ff.x, w[k4 * 4 + 0], a0);
            a1 = fmaf(ff.y, w[k4 * 4 + 1], a1);
            a0 = fmaf(ff.z, w[k4 * 4 + 2], a0);
            a1 = fmaf(ff.w, w[k4 * 4 + 3], a1);
        }
        g_hbias[(size_t)gv * HID + tid] = a0 + a1;
    }
}

// ---------------- wide-N fp16-split GEMM (A linear from accum buffer) ----------------
// D[128,256] = A[M,256] @ B^T; 2-term fp16 split (3 mma terms); B pre-split hi/lo.
// MODE 0: dst = relu(bias + D)           (A = g_accum, dst = g_msg)
// MODE 1: out[gids[row]] += relu(bias+D) (A = g_mplus)
// SMEM per buffer: Ahi 16K | Alo 16K | Bhi 32K | Blo 32K = 96K, double-buffered.
#define MMW_BUF  98304
#define MMW_SMEM (2 * MMW_BUF)

template<int MODE>
__global__ __launch_bounds__(512, 1)
void k_mmw(const float* __restrict__ A, const float* __restrict__ bias,
           const __half* __restrict__ Bhi, const __half* __restrict__ Blo,
           float* __restrict__ dst, const int* __restrict__ gids,
           float* __restrict__ out, int M) {
    extern __shared__ char sm[];
    const int tid  = threadIdx.x;
    const int lane = tid & 31;
    const int wid  = tid >> 5;
    const int wm   = wid >> 2;       // 0..3 : 32-row band
    const int wn   = wid & 3;        // 0..3 : 64-col band
    const int m0   = blockIdx.x * 128;
    const uint32_t sbase = smem_u32(sm);

    float d[2][8][4];
#pragma unroll
    for (int i = 0; i < 2; i++)
#pragma unroll
        for (int j = 0; j < 8; j++)
#pragma unroll
            for (int q = 0; q < 4; q++) d[i][j][q] = 0.f;

    float4 pfA[4];

    auto ldgA = [&](int cc) {
#pragma unroll
        for (int j = 0; j < 4; j++) {
            int idx = tid + j * 512;            // 0..2047
            int row = idx >> 4, seg = idx & 15; // 16 float4-segs = 64 floats
            int gm = m0 + row;
            pfA[j] = make_float4(0.f, 0.f, 0.f, 0.f);
            if (gm < M)
                pfA[j] = __ldg((const float4*)A + (size_t)gm * 64 + cc * 16 + seg);
        }
    };
    auto stsA = [&](int b) {
        char* buf = sm + b * MMW_BUF;
#pragma unroll
        for (int j = 0; j < 4; j++) {
            int idx = tid + j * 512;
            int row = idx >> 4, seg = idx & 15;
            uint32_t off = (uint32_t)(row * 128 + seg * 8);
            uint32_t sw = off ^ ((off >> 3) & 0x70);
            float4 v = pfA[j];
            __half2 h01 = __floats2half2_rn(v.x, v.y);
            __half2 h23 = __floats2half2_rn(v.z, v.w);
            __half2 l01 = __floats2half2_rn(v.x - __low2float(h01), v.y - __high2float(h01));
            __half2 l23 = __floats2half2_rn(v.z - __low2float(h23), v.w - __high2float(h23));
            *(uint2*)(buf + sw)         = make_uint2(h2u(h01), h2u(h23));
            *(uint2*)(buf + 16384 + sw) = make_uint2(h2u(l01), h2u(l23));
        }
    };
    auto cpB = [&](int cc, int b) {
        uint32_t base = sbase + b * MMW_BUF;
#pragma unroll
        for (int j = 0; j < 8; j++) {
            int idx = tid + j * 512;            // 0..4095
            int u = idx & 2047;
            int row = u >> 3, seg = u & 7;      // 8 x 16B per row (128B)
            uint32_t off = (uint32_t)(row * 128 + seg * 16);
            uint32_t sw = off ^ ((off >> 3) & 0x70);
            const __half* src = (idx < 2048) ? Bhi : Blo;
            uint32_t dsm = base + ((idx < 2048) ? 32768u : 65536u) + sw;
            cp16(dsm, src + (size_t)row * 256 + cc * 64 + seg * 8);
        }
        CP_COMMIT();
    };
    auto compute = [&](int b) {
        uint32_t baseA  = sbase + b * MMW_BUF;
        uint32_t baseAl = baseA + 16384;
        uint32_t baseBh = baseA + 32768;
        uint32_t baseBl = baseA + 65536;
        const int r = lane & 7, q = lane >> 3;
#pragma unroll
        for (int s = 0; s < 4; s++) {
            uint32_t ah[2][4], al[2][4];
#pragma unroll
            for (int mt = 0; mt < 2; mt++) {
                uint32_t mrow = (uint32_t)(wm * 32 + mt * 16 + (q & 1) * 8 + r);
                uint32_t off = mrow * 128 + (q >> 1) * 16 + s * 32;
                uint32_t sw = off ^ ((off >> 3) & 0x70);
                ldsm4(ah[mt], baseA + sw);
                ldsm4(al[mt], baseAl + sw);
            }
#pragma unroll
            for (int h = 0; h < 2; h++) {
                uint32_t bh[4][2], bl[4][2];
#pragma unroll
                for (int nt = 0; nt < 4; nt++) {
                    uint32_t nrow = (uint32_t)(wn * 64 + h * 32 + nt * 8 + r);
                    uint32_t off = nrow * 128 + (q & 1) * 16 + s * 32;
                    uint32_t sw = off ^ ((off >> 3) & 0x70);
                    ldsm2(bh[nt], baseBh + sw);
                    ldsm2(bl[nt], baseBl + sw);
                }
#pragma unroll
                for (int mt = 0; mt < 2; mt++)
#pragma unroll
                    for (int nt = 0; nt < 4; nt++) {
                        float* acc = d[mt][h * 4 + nt];
                        mma_f16(acc, ah[mt], bh[nt]);
                        mma_f16(acc, ah[mt], bl[nt]);
                        mma_f16(acc, al[mt], bh[nt]);
                    }
            }
        }
    };

    // prologue
    cpB(0, 0);
    ldgA(0);
    stsA(0);
    CP_WAIT0();
    __syncthreads();

#pragma unroll
    for (int c = 0; c < 4; c++) {
        if (c < 3) {
            cpB(c + 1, (c + 1) & 1);
            ldgA(c + 1);
        }
        compute(c & 1);
        if (c < 3) stsA((c + 1) & 1);
        CP_WAIT0();
        __syncthreads();
    }

    // epilogue
#pragma unroll
    for (int mt = 0; mt < 2; mt++) {
#pragma unroll
        for (int n = 0; n < 8; n++) {
            int row = m0 + wm * 32 + mt * 16 + (lane >> 2);
            int col = wn * 64 + n * 8 + (lane & 3) * 2;
#pragma unroll
            for (int h2 = 0; h2 < 2; h2++) {
                int gr = row + h2 * 8;
                if (gr >= M) continue;
                size_t gb = (size_t)gr * 256 + col;
                float2 bv = *(const float2*)(bias + gb);
                float ox = fmaxf(bv.x + d[mt][n][h2 * 2 + 0], 0.f);
                float oy = fmaxf(bv.y + d[mt][n][h2 * 2 + 1], 0.f);
                if (MODE == 0) {
                    *(float2*)(dst + gb) = make_float2(ox, oy);
                } else {
                    int g = gids[gr];
                    red2(out + (size_t)g * 256 + col, ox, oy);
                }
            }
        }
    }
}

// ---------------- launch ----------------
extern "C" void kernel_launch(void* const* d_in, const int* in_sizes, int n_in,
                              void* d_out, int out_size) {
    (void)in_sizes; (void)n_in; (void)out_size;
    const float* node_x = (const float*)d_in[0];
    const float* bond_x = (const float*)d_in[1];
    const float* tree   = (const float*)d_in[2];
    const float* W_i    = (const float*)d_in[3];
    const float* W_h    = (const float*)d_in[4];
    const float* W_o    = (const float*)d_in[5];
    const float* b_o    = (const float*)d_in[6];
    const int* esrc = (const int*)d_in[7];
    const int* edst = (const int*)d_in[8];
    const int* lsrc = (const int*)d_in[9];
    const int* ldst = (const int*)d_in[10];
    const int* tgt  = (const int*)d_in[11];
    const int* gids = (const int*)d_in[12];
    float* out = (float*)d_out;

    cudaFuncSetAttribute(k_mmw<0>, cudaFuncAttributeMaxDynamicSharedMemorySize, MMW_SMEM);
    cudaFuncSetAttribute(k_mmw<1>, cudaFuncAttributeMaxDynamicSharedMemorySize, MMW_SMEM);

    float *hb_p, *mi_p, *msg_p, *acc_p, *mp_p;
    cudaGetSymbolAddress((void**)&hb_p,  g_hbias);
    cudaGetSymbolAddress((void**)&mi_p,  g_msg_input);
    cudaGetSymbolAddress((void**)&msg_p, g_msg);
    cudaGetSymbolAddress((void**)&acc_p, g_accum);
    cudaGetSymbolAddress((void**)&mp_p,  g_mplus);
    __half *WhH, *WhL, *WoH, *WoL;
    cudaGetSymbolAddress((void**)&WhH, g_WhT_hi);
    cudaGetSymbolAddress((void**)&WhL, g_WhT_lo);
    cudaGetSymbolAddress((void**)&WoH, g_WoT_hi);
    cudaGetSymbolAddress((void**)&WoL, g_WoT_lo);
    int *lg_rp, *lg_cur, *lg_csr_p, *nd_rp, *nd_cur, *nd_csr_p, *part_p, *part2_p;
    cudaGetSymbolAddress((void**)&lg_rp,    g_lg_rowptr);
    cudaGetSymbolAddress((void**)&lg_cur,   g_lg_cursor);
    cudaGetSymbolAddress((void**)&lg_csr_p, g_lg_csr);
    cudaGetSymbolAddress((void**)&nd_rp,    g_nd_rowptr);
    cudaGetSymbolAddress((void**)&nd_cur,   g_nd_cursor);
    cudaGetSymbolAddress((void**)&nd_csr_p, g_nd_csr);
    cudaGetSymbolAddress((void**)&part_p,   g_part);
    cudaGetSymbolAddress((void**)&part2_p,  g_part2);

    // ---- CSR build: line graph (buckets = ldst over N_EDGES) ----
    k_zeroi<<<1172, 256>>>(lg_cur, N_EDGES_C);
    k_hist<<<2344, 256>>>(ldst, lg_cur, N_LG_C);
    k_scan1<<<293, 256>>>(lg_cur, lg_rp, N_EDGES_C, part_p);
    k_scan1<<<1, 256>>>(part_p, part2_p, 293, nullptr);
    k_scan3<<<1172, 256>>>(lg_rp, lg_cur, part2_p, N_EDGES_C, N_LG_C);
    k_fill<<<2344, 256>>>(lsrc, ldst, lg_cur, lg_csr_p, N_LG_C);
    // ---- CSR build: node graph (buckets = edge_dst over N_NODES; values = edge id) ----
    k_zeroi<<<586, 256>>>(nd_cur, N_NODES_C);
    k_hist<<<1172, 256>>>(edst, nd_cur, N_EDGES_C);
    k_scan1<<<147, 256>>>(nd_cur, nd_rp, N_NODES_C, part_p);
    k_scan1<<<1, 256>>>(part_p, part2_p, 147, nullptr);
    k_scan3<<<586, 256>>>(nd_rp, nd_cur, part2_p, N_NODES_C, N_EDGES_C);
    k_fill_id<<<1172, 256>>>(edst, nd_cur, nd_csr_p, N_EDGES_C);

    k_prep_w<<<512, 256>>>(W_h, W_o);
    k_zero_alpha<<<37500, 256>>>();
    k_zero_out<<<512, 256>>>(out);
    k_tree_scatter<<<15000, 256>>>(tree, tgt);
    k_msg_in<<<(N_EDGES_C + 63) / 64, 256>>>(node_x, bond_x, W_i, esrc);
    k_hbias<<<(N_NODES_C + 63) / 64, 256>>>(node_x, W_o, b_o);

    for (int it = 0; it < 3; it++) {
        if (it == 0) k_lg_gather<true><<<75000, 256>>>(esrc);
        else         k_lg_gather<false><<<75000, 256>>>(esrc);
        k_mmw<0><<<2344, 512, MMW_SMEM>>>(acc_p, mi_p, WhH, WhL, msg_p,
                                          nullptr, nullptr, N_EDGES_C);
    }

    k_node_gather<<<37500, 256>>>();
    k_counts<<<586, 256>>>(gids);
    k_mmw<1><<<1172, 512, MMW_SMEM>>>(mp_p, hb_p, WoH, WoL, nullptr,
                                      gids, out, N_NODES_C);
    k_div<<<512, 256>>>(out);
}

// round 9
// speedup vs baseline: 1.3420x; 1.0405x over previous
#include <cuda_runtime.h>
#include <cuda_fp16.h>
#include <cstdint>

#define N_NODES_C 150000
#define N_EDGES_C 300000
#define N_LG_C    600000
#define HID       256
#define NGRAPH    2048
#define AFD       35
#define BFD       5
#define KIN       40

// ---------------- scratch (static device globals; no allocation) ----------------
__device__ float g_msg_input[(size_t)N_EDGES_C * HID];
__device__ float g_msg      [(size_t)N_EDGES_C * HID];
__device__ float g_accum    [(size_t)N_EDGES_C * HID];
__device__ float g_alpha    [(size_t)N_NODES_C * HID];
__device__ float g_mplus    [(size_t)N_NODES_C * HID];
__device__ float g_hbias    [(size_t)N_NODES_C * HID];
__device__ __half g_WhT_hi  [HID * HID];
__device__ __half g_WhT_lo  [HID * HID];
__device__ __half g_WoT_hi  [HID * HID];
__device__ __half g_WoT_lo  [HID * HID];
__device__ float g_counts   [NGRAPH];

// CSR structures
__device__ int g_lg_rowptr[N_EDGES_C + 1];
__device__ int g_lg_cursor[N_EDGES_C];
__device__ int g_lg_csr[N_LG_C];
__device__ int g_nd_rowptr[N_NODES_C + 1];
__device__ int g_nd_cursor[N_NODES_C];
__device__ int g_nd_csr[N_EDGES_C];
__device__ int g_part [1024];
__device__ int g_part2[1024];

// ---------------- PTX helpers (portable: sm_80/sm_90 level only) ----------------
__device__ __forceinline__ uint32_t smem_u32(const void* p) {
    uint32_t a;
    asm("{ .reg .u64 t; cvta.to.shared.u64 t, %1; cvt.u32.u64 %0, t; }" : "=r"(a) : "l"(p));
    return a;
}
__device__ __forceinline__ void red4(float* p, float a, float b, float c, float d) {
    asm volatile("red.global.add.v4.f32 [%0], {%1, %2, %3, %4};"
                 :: "l"(p), "f"(a), "f"(b), "f"(c), "f"(d) : "memory");
}
__device__ __forceinline__ void red2(float* p, float a, float b) {
    asm volatile("red.global.add.v2.f32 [%0], {%1, %2};"
                 :: "l"(p), "f"(a), "f"(b) : "memory");
}
__device__ __forceinline__ void ldsm4(uint32_t* r, uint32_t addr) {
    asm volatile("ldmatrix.sync.aligned.m8n8.x4.shared.b16 {%0,%1,%2,%3}, [%4];"
                 : "=r"(r[0]), "=r"(r[1]), "=r"(r[2]), "=r"(r[3]) : "r"(addr));
}
__device__ __forceinline__ void mma_f16(float* d, const uint32_t* a, const uint32_t* b) {
    asm volatile(
        "mma.sync.aligned.m16n8k16.row.col.f32.f16.f16.f32 "
        "{%0,%1,%2,%3}, {%4,%5,%6,%7}, {%8,%9}, {%0,%1,%2,%3};"
        : "+f"(d[0]), "+f"(d[1]), "+f"(d[2]), "+f"(d[3])
        : "r"(a[0]), "r"(a[1]), "r"(a[2]), "r"(a[3]), "r"(b[0]), "r"(b[1]));
}
__device__ __forceinline__ uint32_t h2u(__half2 h) { return *reinterpret_cast<uint32_t*>(&h); }
__device__ __forceinline__ void cp16(uint32_t dst, const void* src) {
    asm volatile("cp.async.cg.shared.global [%0], [%1], 16;" :: "r"(dst), "l"(src));
}
#define CP_COMMIT() asm volatile("cp.async.commit_group;" ::: "memory")
#define CP_WAIT0()  asm volatile("cp.async.wait_group 0;" ::: "memory")

// ---------------- CSR build kernels ----------------
__global__ void k_zeroi(int* __restrict__ p, int n) {
    int i = blockIdx.x * 256 + threadIdx.x;
    if (i < n) p[i] = 0;
}
__global__ void k_hist(const int* __restrict__ dst, int* __restrict__ cnt, int n) {
    int i = blockIdx.x * 256 + threadIdx.x;
    if (i < n) atomicAdd(&cnt[dst[i]], 1);
}
__global__ void k_scan1(const int* __restrict__ cnt, int* __restrict__ ex, int n,
                        int* __restrict__ part) {
    __shared__ int sh[256];
    int base = blockIdx.x * 1024;
    int t = threadIdx.x;
    int v[4], s = 0;
#pragma unroll
    for (int j = 0; j < 4; j++) {
        int i = base + t * 4 + j;
        v[j] = (i < n) ? cnt[i] : 0;
        s += v[j];
    }
    sh[t] = s;
    __syncthreads();
    for (int off = 1; off < 256; off <<= 1) {
        int x = (t >= off) ? sh[t - off] : 0;
        __syncthreads();
        sh[t] += x;
        __syncthreads();
    }
    int run = (t > 0) ? sh[t - 1] : 0;
    if (part && t == 255) part[blockIdx.x] = sh[255];
#pragma unroll
    for (int j = 0; j < 4; j++) {
        int i = base + t * 4 + j;
        if (i < n) ex[i] = run;
        run += v[j];
    }
}
__global__ void k_scan3(int* __restrict__ ex, int* __restrict__ cursor,
                        const int* __restrict__ part2, int n, int ntot) {
    int i = blockIdx.x * 256 + threadIdx.x;
    if (i < n) {
        int v = ex[i] + part2[i >> 10];
        ex[i] = v;
        cursor[i] = v;
    }
    if (i == 0) ex[n] = ntot;
}
__global__ void k_fill(const int* __restrict__ src, const int* __restrict__ dst,
                       int* __restrict__ cursor, int* __restrict__ csr, int n) {
    int i = blockIdx.x * 256 + threadIdx.x;
    if (i < n) {
        int pos = atomicAdd(&cursor[dst[i]], 1);
        csr[pos] = src[i];
    }
}
__global__ void k_fill_id(const int* __restrict__ dst, int* __restrict__ cursor,
                          int* __restrict__ csr, int n) {
    int i = blockIdx.x * 256 + threadIdx.x;
    if (i < n) {
        int pos = atomicAdd(&cursor[dst[i]], 1);
        csr[pos] = i;
    }
}

// ---------------- utility kernels ----------------
__global__ void k_zero_alpha() {
    int i = blockIdx.x * 256 + threadIdx.x;
    ((float4*)g_alpha)[i] = make_float4(0.f, 0.f, 0.f, 0.f);
}
__global__ void k_zero_out(float* __restrict__ out) {
    int i = blockIdx.x * 256 + threadIdx.x;
    ((float4*)out)[i] = make_float4(0.f, 0.f, 0.f, 0.f);
    if (i < NGRAPH) g_counts[i] = 0.f;
}
__global__ void k_counts(const int* __restrict__ gids) {
    int v = blockIdx.x * 256 + threadIdx.x;
    if (v < N_NODES_C) atomicAdd(&g_counts[gids[v]], 1.0f);
}
__global__ void k_div(float* __restrict__ out) {
    int i = blockIdx.x * 256 + threadIdx.x;
    int g = i >> 6;
    float c = fmaxf(g_counts[g], 1.0f);
    float4 v = ((float4*)out)[i];
    v.x /= c; v.y /= c; v.z /= c; v.w /= c;
    ((float4*)out)[i] = v;
}
// pre-split W to fp16 hi/lo, transposed to [n][k]
__global__ void k_prep_w(const float* __restrict__ Wh, const float* __restrict__ Wo) {
    int n = blockIdx.x & 255;
    int k = threadIdx.x;
    float v;
    __half* hi;
    __half* lo;
    if (blockIdx.x < 256) { v = Wh[k * 256 + n];         hi = g_WhT_hi; lo = g_WhT_lo; }
    else                  { v = Wo[(AFD + k) * 256 + n]; hi = g_WoT_hi; lo = g_WoT_lo; }
    __half h = __float2half_rn(v);
    hi[n * 256 + k] = h;
    lo[n * 256 + k] = __float2half_rn(v - __half2float(h));
}
__global__ void k_tree_scatter(const float* __restrict__ tree, const int* __restrict__ tgt) {
    int i = blockIdx.x * 256 + threadIdx.x;
    int t = i >> 6, q = i & 63;
    float4 v = ((const float4*)tree)[(size_t)t * 64 + q];
    red4(g_alpha + (size_t)tgt[t] * HID + q * 4, v.x, v.y, v.z, v.w);
}

// ---------------- CSR gather: accum[e] = alpha[esrc[e]] + sum msg[lg_csr[...]] --------
template<bool FIRST>
__global__ __launch_bounds__(256)
void k_lg_gather(const int* __restrict__ esrc) {
    int i = blockIdx.x * 256 + threadIdx.x;
    int e = i >> 6, q = i & 63;
    int a = __ldg(&esrc[e]);
    float4 acc = ((const float4*)g_alpha)[(size_t)a * 64 + q];
    int beg = __ldg(&g_lg_rowptr[e]);
    int end = __ldg(&g_lg_rowptr[e + 1]);
    const float4* src = FIRST ? (const float4*)g_msg_input : (const float4*)g_msg;
    for (int j = beg; j < end; j++) {
        int s = __ldg(&g_lg_csr[j]);
        float4 v = src[(size_t)s * 64 + q];
        if (FIRST) {
            v.x = fmaxf(v.x, 0.f); v.y = fmaxf(v.y, 0.f);
            v.z = fmaxf(v.z, 0.f); v.w = fmaxf(v.w, 0.f);
        }
        acc.x += v.x; acc.y += v.y; acc.z += v.z; acc.w += v.w;
    }
    ((float4*)g_accum)[(size_t)e * 64 + q] = acc;
}

// mplus[v] = alpha[v] + sum msg[nd_csr[...]]
__global__ __launch_bounds__(256)
void k_node_gather() {
    int i = blockIdx.x * 256 + threadIdx.x;
    int v = i >> 6, q = i & 63;
    float4 acc = ((const float4*)g_alpha)[(size_t)v * 64 + q];
    int beg = __ldg(&g_nd_rowptr[v]);
    int end = __ldg(&g_nd_rowptr[v + 1]);
    for (int j = beg; j < end; j++) {
        int s = __ldg(&g_nd_csr[j]);
        float4 m = ((const float4*)g_msg)[(size_t)s * 64 + q];
        acc.x += m.x; acc.y += m.y; acc.z += m.z; acc.w += m.w;
    }
    ((float4*)g_mplus)[(size_t)v * 64 + q] = acc;
}

// ---------------- msg_input = [node_x[src]; bond_x] @ W_i ----------------
__global__ __launch_bounds__(256)
void k_msg_in(const float* __restrict__ node_x, const float* __restrict__ bond_x,
              const float* __restrict__ W_i, const int* __restrict__ esrc) {
    __shared__ float feat[64][KIN];
    int e0 = blockIdx.x * 64;
    int tid = threadIdx.x;
    float w[KIN];
#pragma unroll
    for (int k = 0; k < KIN; k++) w[k] = W_i[k * HID + tid];
    for (int idx = tid; idx < 64 * KIN; idx += 256) {
        int e = idx / KIN, k = idx % KIN;
        int ge = e0 + e;
        float vv = 0.f;
        if (ge < N_EDGES_C)
            vv = (k < AFD) ? node_x[(size_t)esrc[ge] * AFD + k]
                           : bond_x[(size_t)ge * BFD + (k - AFD)];
        feat[e][k] = vv;
    }
    __syncthreads();
    for (int e = 0; e < 64; e++) {
        int ge = e0 + e;
        if (ge >= N_EDGES_C) break;
        const float4* f4 = (const float4*)feat[e];
        float a0 = 0.f, a1 = 0.f;
#pragma unroll
        for (int k4 = 0; k4 < KIN / 4; k4++) {
            float4 ff = f4[k4];
            a0 = fmaf(ff.x, w[k4 * 4 + 0], a0);
            a1 = fmaf(ff.y, w[k4 * 4 + 1], a1);
            a0 = fmaf(ff.z, w[k4 * 4 + 2], a0);
            a1 = fmaf(ff.w, w[k4 * 4 + 3], a1);
        }
        g_msg_input[(size_t)ge * HID + tid] = a0 + a1;
    }
}

// ---------------- g_hbias = node_x @ W_o[:35] + b_o ----------------
__global__ __launch_bounds__(256)
void k_hbias(const float* __restrict__ node_x, const float* __restrict__ W_o,
             const float* __restrict__ b_o) {
    __shared__ float feat[64][36];
    int v0 = blockIdx.x * 64;
    int tid = threadIdx.x;
    float w[36];
#pragma unroll
    for (int k = 0; k < AFD; k++) w[k] = W_o[k * HID + tid];
    w[35] = 0.f;
    float bb = b_o[tid];
    for (int idx = tid; idx < 64 * 36; idx += 256) {
        int v = idx / 36, k = idx % 36;
        int gv = v0 + v;
        feat[v][k] = (gv < N_NODES_C && k < AFD) ? node_x[(size_t)gv * AFD + k] : 0.f;
    }
    __syncthreads();
    for (int v = 0; v < 64; v++) {
        int gv = v0 + v;
        if (gv >= N_NODES_C) break;
        const float4* f4 = (const float4*)feat[v];
        float a0 = bb, a1 = 0.f;
#pragma unroll
        for (int k4 = 0; k4 < 9; k4++) {
            float4 ff = f4[k4];
            a0 = fmaf(ff.x, w[k4 * 4 + 0], a0);
            a1 = fmaf(ff.y, w[k4 * 4 + 1], a1);
            a0 = fmaf(ff.z, w[k4 * 4 + 2], a0);
            a1 = fmaf(ff.w, w[k4 * 4 + 3], a1);
        }
        g_hbias[(size_t)gv * HID + tid] = a0 + a1;
    }
}

// ---------------- wide-N fp16-split GEMM (A linear from accum buffer) ----------------
// D[128,256] = A[M,256] @ B^T; 2-term fp16 split (3 mma terms); B pre-split hi/lo.
// B fragments loaded 2 n-tiles at a time via ldmatrix.x4 (halves B LDSM count).
// MODE 0: dst = relu(bias + D)           (A = g_accum, dst = g_msg)
// MODE 1: out[gids[row]] += relu(bias+D) (A = g_mplus)
// SMEM per buffer: Ahi 16K | Alo 16K | Bhi 32K | Blo 32K = 96K, double-buffered.
#define MMW_BUF  98304
#define MMW_SMEM (2 * MMW_BUF)

template<int MODE>
__global__ __launch_bounds__(512, 1)
void k_mmw(const float* __restrict__ A, const float* __restrict__ bias,
           const __half* __restrict__ Bhi, const __half* __restrict__ Blo,
           float* __restrict__ dst, const int* __restrict__ gids,
           float* __restrict__ out, int M) {
    extern __shared__ char sm[];
    const int tid  = threadIdx.x;
    const int lane = tid & 31;
    const int wid  = tid >> 5;
    const int wm   = wid >> 2;       // 0..3 : 32-row band
    const int wn   = wid & 3;        // 0..3 : 64-col band
    const int m0   = blockIdx.x * 128;
    const uint32_t sbase = smem_u32(sm);

    float d[2][8][4];
#pragma unroll
    for (int i = 0; i < 2; i++)
#pragma unroll
        for (int j = 0; j < 8; j++)
#pragma unroll
            for (int q = 0; q < 4; q++) d[i][j][q] = 0.f;

    float4 pfA[4];

    auto ldgA = [&](int cc) {
#pragma unroll
        for (int j = 0; j < 4; j++) {
            int idx = tid + j * 512;            // 0..2047
            int row = idx >> 4, seg = idx & 15; // 16 float4-segs = 64 floats
            int gm = m0 + row;
            pfA[j] = make_float4(0.f, 0.f, 0.f, 0.f);
            if (gm < M)
                pfA[j] = __ldg((const float4*)A + (size_t)gm * 64 + cc * 16 + seg);
        }
    };
    auto stsA = [&](int b) {
        char* buf = sm + b * MMW_BUF;
#pragma unroll
        for (int j = 0; j < 4; j++) {
            int idx = tid + j * 512;
            int row = idx >> 4, seg = idx & 15;
            uint32_t off = (uint32_t)(row * 128 + seg * 8);
            uint32_t sw = off ^ ((off >> 3) & 0x70);
            float4 v = pfA[j];
            __half2 h01 = __floats2half2_rn(v.x, v.y);
            __half2 h23 = __floats2half2_rn(v.z, v.w);
            __half2 l01 = __floats2half2_rn(v.x - __low2float(h01), v.y - __high2float(h01));
            __half2 l23 = __floats2half2_rn(v.z - __low2float(h23), v.w - __high2float(h23));
            *(uint2*)(buf + sw)         = make_uint2(h2u(h01), h2u(h23));
            *(uint2*)(buf + 16384 + sw) = make_uint2(h2u(l01), h2u(l23));
        }
    };
    auto cpB = [&](int cc, int b) {
        uint32_t base = sbase + b * MMW_BUF;
#pragma unroll
        for (int j = 0; j < 8; j++) {
            int idx = tid + j * 512;            // 0..4095
            int u = idx & 2047;
            int row = u >> 3, seg = u & 7;      // 8 x 16B per row (128B)
            uint32_t off = (uint32_t)(row * 128 + seg * 16);
            uint32_t sw = off ^ ((off >> 3) & 0x70);
            const __half* src = (idx < 2048) ? Bhi : Blo;
            uint32_t dsm = base + ((idx < 2048) ? 32768u : 65536u) + sw;
            cp16(dsm, src + (size_t)row * 256 + cc * 64 + seg * 8);
        }
        CP_COMMIT();
    };
    auto compute = [&](int b) {
        uint32_t baseA  = sbase + b * MMW_BUF;
        uint32_t baseAl = baseA + 16384;
        uint32_t baseBh = baseA + 32768;
        uint32_t baseBl = baseA + 65536;
        const int r = lane & 7, q = lane >> 3;
        // B ldmatrix.x4 addressing: lane group g (0..3) supplies rows for matrix g:
        //   g=0: n-tile nt,   k-phase 0   g=1: n-tile nt,   k-phase 1
        //   g=2: n-tile nt+1, k-phase 0   g=3: n-tile nt+1, k-phase 1
        const int bro = ((q >> 1) << 3) + r;   // row offset within the nt-pair
        const int bkp = (q & 1) << 4;          // k-phase byte offset
#pragma unroll
        for (int s = 0; s < 4; s++) {
            uint32_t ah[2][4], al[2][4];
#pragma unroll
            for (int mt = 0; mt < 2; mt++) {
                uint32_t mrow = (uint32_t)(wm * 32 + mt * 16 + (q & 1) * 8 + r);
                uint32_t off = mrow * 128 + (q >> 1) * 16 + s * 32;
                uint32_t sw = off ^ ((off >> 3) & 0x70);
                ldsm4(ah[mt], baseA + sw);
                ldsm4(al[mt], baseAl + sw);
            }
#pragma unroll
            for (int h = 0; h < 2; h++) {
                uint32_t bh4[2][4], bl4[2][4];
#pragma unroll
                for (int ntp = 0; ntp < 2; ntp++) {
                    uint32_t nrow = (uint32_t)(wn * 64 + h * 32 + ntp * 16 + bro);
                    uint32_t off = nrow * 128 + bkp + s * 32;
                    uint32_t sw = off ^ ((off >> 3) & 0x70);
                    ldsm4(bh4[ntp], baseBh + sw);
                    ldsm4(bl4[ntp], baseBl + sw);
                }
#pragma unroll
                for (int mt = 0; mt < 2; mt++)
#pragma unroll
                    for (int nt = 0; nt < 4; nt++) {
                        float* acc = d[mt][h * 4 + nt];
                        const uint32_t* bhp = &bh4[nt >> 1][(nt & 1) * 2];
                        const uint32_t* blp = &bl4[nt >> 1][(nt & 1) * 2];
                        mma_f16(acc, ah[mt], bhp);
                        mma_f16(acc, ah[mt], blp);
                        mma_f16(acc, al[mt], bhp);
                    }
            }
        }
    };

    // prologue
    cpB(0, 0);
    ldgA(0);
    stsA(0);
    CP_WAIT0();
    __syncthreads();

#pragma unroll
    for (int c = 0; c < 4; c++) {
        if (c < 3) {
            cpB(c + 1, (c + 1) & 1);
            ldgA(c + 1);
        }
        compute(c & 1);
        if (c < 3) stsA((c + 1) & 1);
        CP_WAIT0();
        __syncthreads();
    }

    // epilogue
#pragma unroll
    for (int mt = 0; mt < 2; mt++) {
#pragma unroll
        for (int n = 0; n < 8; n++) {
            int row = m0 + wm * 32 + mt * 16 + (lane >> 2);
            int col = wn * 64 + n * 8 + (lane & 3) * 2;
#pragma unroll
            for (int h2 = 0; h2 < 2; h2++) {
                int gr = row + h2 * 8;
                if (gr >= M) continue;
                size_t gb = (size_t)gr * 256 + col;
                float2 bv = *(const float2*)(bias + gb);
                float ox = fmaxf(bv.x + d[mt][n][h2 * 2 + 0], 0.f);
                float oy = fmaxf(bv.y + d[mt][n][h2 * 2 + 1], 0.f);
                if (MODE == 0) {
                    *(float2*)(dst + gb) = make_float2(ox, oy);
                } else {
                    int g = gids[gr];
                    red2(out + (size_t)g * 256 + col, ox, oy);
                }
            }
        }
    }
}

// ---------------- launch ----------------
extern "C" void kernel_launch(void* const* d_in, const int* in_sizes, int n_in,
                              void* d_out, int out_size) {
    (void)in_sizes; (void)n_in; (void)out_size;
    const float* node_x = (const float*)d_in[0];
    const float* bond_x = (const float*)d_in[1];
    const float* tree   = (const float*)d_in[2];
    const float* W_i    = (const float*)d_in[3];
    const float* W_h    = (const float*)d_in[4];
    const float* W_o    = (const float*)d_in[5];
    const float* b_o    = (const float*)d_in[6];
    const int* esrc = (const int*)d_in[7];
    const int* edst = (const int*)d_in[8];
    const int* lsrc = (const int*)d_in[9];
    const int* ldst = (const int*)d_in[10];
    const int* tgt  = (const int*)d_in[11];
    const int* gids = (const int*)d_in[12];
    float* out = (float*)d_out;

    cudaFuncSetAttribute(k_mmw<0>, cudaFuncAttributeMaxDynamicSharedMemorySize, MMW_SMEM);
    cudaFuncSetAttribute(k_mmw<1>, cudaFuncAttributeMaxDynamicSharedMemorySize, MMW_SMEM);

    float *hb_p, *mi_p, *msg_p, *acc_p, *mp_p;
    cudaGetSymbolAddress((void**)&hb_p,  g_hbias);
    cudaGetSymbolAddress((void**)&mi_p,  g_msg_input);
    cudaGetSymbolAddress((void**)&msg_p, g_msg);
    cudaGetSymbolAddress((void**)&acc_p, g_accum);
    cudaGetSymbolAddress((void**)&mp_p,  g_mplus);
    __half *WhH, *WhL, *WoH, *WoL;
    cudaGetSymbolAddress((void**)&WhH, g_WhT_hi);
    cudaGetSymbolAddress((void**)&WhL, g_WhT_lo);
    cudaGetSymbolAddress((void**)&WoH, g_WoT_hi);
    cudaGetSymbolAddress((void**)&WoL, g_WoT_lo);
    int *lg_rp, *lg_cur, *lg_csr_p, *nd_rp, *nd_cur, *nd_csr_p, *part_p, *part2_p;
    cudaGetSymbolAddress((void**)&lg_rp,    g_lg_rowptr);
    cudaGetSymbolAddress((void**)&lg_cur,   g_lg_cursor);
    cudaGetSymbolAddress((void**)&lg_csr_p, g_lg_csr);
    cudaGetSymbolAddress((void**)&nd_rp,    g_nd_rowptr);
    cudaGetSymbolAddress((void**)&nd_cur,   g_nd_cursor);
    cudaGetSymbolAddress((void**)&nd_csr_p, g_nd_csr);
    cudaGetSymbolAddress((void**)&part_p,   g_part);
    cudaGetSymbolAddress((void**)&part2_p,  g_part2);

    // ---- CSR build: line graph (buckets = ldst over N_EDGES) ----
    k_zeroi<<<1172, 256>>>(lg_cur, N_EDGES_C);
    k_hist<<<2344, 256>>>(ldst, lg_cur, N_LG_C);
    k_scan1<<<293, 256>>>(lg_cur, lg_rp, N_EDGES_C, part_p);
    k_scan1<<<1, 256>>>(part_p, part2_p, 293, nullptr);
    k_scan3<<<1172, 256>>>(lg_rp, lg_cur, part2_p, N_EDGES_C, N_LG_C);
    k_fill<<<2344, 256>>>(lsrc, ldst, lg_cur, lg_csr_p, N_LG_C);
    // ---- CSR build: node graph (buckets = edge_dst over N_NODES; values = edge id) ----
    k_zeroi<<<586, 256>>>(nd_cur, N_NODES_C);
    k_hist<<<1172, 256>>>(edst, nd_cur, N_EDGES_C);
    k_scan1<<<147, 256>>>(nd_cur, nd_rp, N_NODES_C, part_p);
    k_scan1<<<1, 256>>>(part_p, part2_p, 147, nullptr);
    k_scan3<<<586, 256>>>(nd_rp, nd_cur, part2_p, N_NODES_C, N_EDGES_C);
    k_fill_id<<<1172, 256>>>(edst, nd_cur, nd_csr_p, N_EDGES_C);

    k_prep_w<<<512, 256>>>(W_h, W_o);
    k_zero_alpha<<<37500, 256>>>();
    k_zero_out<<<512, 256>>>(out);
    k_tree_scatter<<<15000, 256>>>(tree, tgt);
    k_msg_in<<<(N_EDGES_C + 63) / 64, 256>>>(node_x, bond_x, W_i, esrc);
    k_hbias<<<(N_NODES_C + 63) / 64, 256>>>(node_x, W_o, b_o);

    for (int it = 0; it < 3; it++) {
        if (it == 0) k_lg_gather<true><<<75000, 256>>>(esrc);
        else         k_lg_gather<false><<<75000, 256>>>(esrc);
        k_mmw<0><<<2344, 512, MMW_SMEM>>>(acc_p, mi_p, WhH, WhL, msg_p,
                                          nullptr, nullptr, N_EDGES_C);
    }

    k_node_gather<<<37500, 256>>>();
    k_counts<<<586, 256>>>(gids);
    k_mmw<1><<<1172, 512, MMW_SMEM>>>(mp_p, hb_p, WoH, WoL, nullptr,
                                      gids, out, N_NODES_C);
    k_div<<<512, 256>>>(out);
}